// round 1
// baseline (speedup 1.0000x reference)
#include <cuda_runtime.h>
#include <math_constants.h>

// Problem constants
constexpr int BATCH = 4;
constexpr int CCH   = 256;     // channels
constexpr int HH    = 64;
constexpr int WW    = 64;
constexpr int HWSZ  = HH * WW; // 4096
constexpr int KCONV = CCH * 9; // 2304 (implicit-GEMM K for conv)

// Scratch (allocation-free rule: __device__ globals)
__device__ float g_x1[(size_t)BATCH * CCH * HWSZ];           // relu(conv(ref, w1))  [B,C,HW]
__device__ float g_v [(size_t)BATCH * CCH * HWSZ];           // relu(conv(ref, w2))  [B,C,HW]
__device__ float g_S [(size_t)BATCH * HWSZ * HWSZ];          // scores / P (in place) 268 MB

// ---------------------------------------------------------------------------
// Kernel 1: 3x3 SAME conv + ReLU as implicit GEMM.
//   out[m = o][n = b*HW + s] = relu( sum_k W[m][k] * im2col[k][n] )
//   M = 256, N = 16384, K = 2304. 128x128 block tile, k-step 8, 8x8 per thread.
// ---------------------------------------------------------------------------
__global__ __launch_bounds__(256) void conv_relu_kernel(
    const float* __restrict__ in,    // [B,C,H,W]
    const float* __restrict__ wgt,   // [O=256][2304] row-major (== [O,I,3,3])
    float* __restrict__ out)         // [B,C,HW]
{
    __shared__ float As[8][132];     // As[k][m]  (padded: conflict-free transposed store)
    __shared__ float Bs[8][128];     // Bs[k][n]

    const int tid = threadIdx.x;
    const int tx  = tid & 15;
    const int ty  = tid >> 4;
    const int n0  = blockIdx.x * 128;
    const int m0  = blockIdx.y * 128;

    float acc[8][8];
    #pragma unroll
    for (int i = 0; i < 8; ++i)
        #pragma unroll
        for (int j = 0; j < 8; ++j) acc[i][j] = 0.f;

    for (int k0 = 0; k0 < KCONV; k0 += 8) {
        // --- load weight tile (coalesced 32B rows) ---
        #pragma unroll
        for (int j = 0; j < 4; ++j) {
            int e = tid * 4 + j;
            int m = e >> 3, k = e & 7;
            As[k][m] = wgt[(size_t)(m0 + m) * KCONV + k0 + k];
        }
        // --- gather im2col tile (coalesced along n) ---
        #pragma unroll
        for (int r = 0; r < 4; ++r) {
            int e  = tid + 256 * r;
            int k  = e >> 7, n = e & 127;
            int kk = k0 + k;
            int ic  = kk / 9;
            int rem = kk - ic * 9;
            int ky  = rem / 3;
            int kx  = rem - ky * 3;
            int nn = n0 + n;
            int b  = nn >> 12;
            int s  = nn & 4095;
            int y  = s >> 6, x = s & 63;
            int yy = y + ky - 1, xx = x + kx - 1;
            float v = 0.f;
            if ((unsigned)yy < (unsigned)HH && (unsigned)xx < (unsigned)WW)
                v = in[(((size_t)(b * CCH + ic)) * HH + yy) * WW + xx];
            Bs[k][n] = v;
        }
        __syncthreads();

        #pragma unroll
        for (int k = 0; k < 8; ++k) {
            float a[8], bb[8];
            #pragma unroll
            for (int i = 0; i < 8; ++i) a[i]  = As[k][ty * 8 + i];
            #pragma unroll
            for (int j = 0; j < 8; ++j) bb[j] = Bs[k][tx * 8 + j];
            #pragma unroll
            for (int i = 0; i < 8; ++i)
                #pragma unroll
                for (int j = 0; j < 8; ++j)
                    acc[i][j] = fmaf(a[i], bb[j], acc[i][j]);
        }
        __syncthreads();
    }

    #pragma unroll
    for (int i = 0; i < 8; ++i) {
        int m = m0 + ty * 8 + i;
        #pragma unroll
        for (int j = 0; j < 8; ++j) {
            int nn = n0 + tx * 8 + j;
            int b  = nn >> 12, s = nn & 4095;
            float v = acc[i][j];
            out[((size_t)(b * CCH + m)) * HWSZ + s] = v > 0.f ? v : 0.f;
        }
    }
}

// ---------------------------------------------------------------------------
// Kernel 2: Gram matrix S = X^T X per batch.  S[n][m] = sum_c X[c][n]*X[c][m]
//   M = N = 4096, K = 256.  Both operand tiles load coalesced from X rows.
// ---------------------------------------------------------------------------
__global__ __launch_bounds__(256) void gram_kernel(
    const float* __restrict__ X,   // [B,C,HW]
    float* __restrict__ S)         // [B,HW,HW]
{
    const int b = blockIdx.z;
    const float* Xb = X + (size_t)b * CCH * HWSZ;
    float* Sb = S + (size_t)b * HWSZ * HWSZ;

    __shared__ float As[8][128];   // As[k][n]
    __shared__ float Bs[8][128];   // Bs[k][m]

    const int tid = threadIdx.x;
    const int tx  = tid & 15;
    const int ty  = tid >> 4;
    const int m0  = blockIdx.x * 128;
    const int n0  = blockIdx.y * 128;

    float acc[8][8];
    #pragma unroll
    for (int i = 0; i < 8; ++i)
        #pragma unroll
        for (int j = 0; j < 8; ++j) acc[i][j] = 0.f;

    for (int k0 = 0; k0 < CCH; k0 += 8) {
        #pragma unroll
        for (int r = 0; r < 4; ++r) {
            int e = tid + 256 * r;
            int k = e >> 7, p = e & 127;
            As[k][p] = Xb[(size_t)(k0 + k) * HWSZ + n0 + p];
            Bs[k][p] = Xb[(size_t)(k0 + k) * HWSZ + m0 + p];
        }
        __syncthreads();
        #pragma unroll
        for (int k = 0; k < 8; ++k) {
            float a[8], bb[8];
            #pragma unroll
            for (int i = 0; i < 8; ++i) a[i]  = As[k][ty * 8 + i];
            #pragma unroll
            for (int j = 0; j < 8; ++j) bb[j] = Bs[k][tx * 8 + j];
            #pragma unroll
            for (int i = 0; i < 8; ++i)
                #pragma unroll
                for (int j = 0; j < 8; ++j)
                    acc[i][j] = fmaf(a[i], bb[j], acc[i][j]);
        }
        __syncthreads();
    }

    #pragma unroll
    for (int i = 0; i < 8; ++i) {
        size_t row = (size_t)(n0 + ty * 8 + i) * HWSZ;
        #pragma unroll
        for (int j = 0; j < 8; ++j)
            Sb[row + m0 + tx * 8 + j] = acc[i][j];
    }
}

// ---------------------------------------------------------------------------
// Kernel 3: row softmax of S in place (S symmetric => this equals corr^T).
//   One block per row (4096 floats), 16 elems/thread kept in registers.
// ---------------------------------------------------------------------------
__device__ __forceinline__ float warpMax(float v) {
    #pragma unroll
    for (int o = 16; o; o >>= 1) v = fmaxf(v, __shfl_xor_sync(0xffffffffu, v, o));
    return v;
}
__device__ __forceinline__ float warpSum(float v) {
    #pragma unroll
    for (int o = 16; o; o >>= 1) v += __shfl_xor_sync(0xffffffffu, v, o);
    return v;
}

__global__ __launch_bounds__(256) void softmax_kernel(float* __restrict__ S)
{
    float* p = S + (size_t)blockIdx.y * HWSZ * HWSZ + (size_t)blockIdx.x * HWSZ;
    const int tid = threadIdx.x;
    __shared__ float red[8];

    float vals[16];
    float mx = -CUDART_INF_F;
    #pragma unroll
    for (int i = 0; i < 16; ++i) {
        vals[i] = p[tid + i * 256];
        mx = fmaxf(mx, vals[i]);
    }
    mx = warpMax(mx);
    if ((tid & 31) == 0) red[tid >> 5] = mx;
    __syncthreads();
    {
        float m = red[tid & 7];
        #pragma unroll
        for (int o = 4; o; o >>= 1) m = fmaxf(m, __shfl_xor_sync(0xffffffffu, m, o));
        mx = m;
    }

    float sum = 0.f;
    #pragma unroll
    for (int i = 0; i < 16; ++i) {
        vals[i] = __expf(vals[i] - mx);
        sum += vals[i];
    }
    sum = warpSum(sum);
    __syncthreads();
    if ((tid & 31) == 0) red[tid >> 5] = sum;
    __syncthreads();
    {
        float s = red[tid & 7];
        #pragma unroll
        for (int o = 4; o; o >>= 1) s += __shfl_xor_sync(0xffffffffu, s, o);
        sum = s;
    }

    float inv = 1.f / sum;
    #pragma unroll
    for (int i = 0; i < 16; ++i)
        p[tid + i * 256] = vals[i] * inv;
}

// ---------------------------------------------------------------------------
// Kernel 4: A = V * P^T per batch, fused epilogue out = gamma*A + ref.
//   A[c][m] = sum_n V[c][n] * P[m][n].  M = 256(C), N = 4096(m), K = 4096(n).
// ---------------------------------------------------------------------------
__global__ __launch_bounds__(256) void av_kernel(
    const float* __restrict__ V,      // [B,C,HW]
    const float* __restrict__ P,      // [B,HW,HW]
    const float* __restrict__ ref,    // [B,C,HW]
    const float* __restrict__ gammap, // scalar
    float* __restrict__ out)          // [B,C,HW]
{
    const int b = blockIdx.z;
    const float* Vb = V + (size_t)b * CCH * HWSZ;
    const float* Pb = P + (size_t)b * HWSZ * HWSZ;

    __shared__ float As[8][132];   // As[k][c]
    __shared__ float Bs[8][132];   // Bs[k][m]

    const int tid = threadIdx.x;
    const int tx  = tid & 15;
    const int ty  = tid >> 4;
    const int m0  = blockIdx.x * 128;
    const int c0  = blockIdx.y * 128;

    float acc[8][8];
    #pragma unroll
    for (int i = 0; i < 8; ++i)
        #pragma unroll
        for (int j = 0; j < 8; ++j) acc[i][j] = 0.f;

    for (int k0 = 0; k0 < HWSZ; k0 += 8) {
        #pragma unroll
        for (int j = 0; j < 4; ++j) {
            int e = tid * 4 + j;
            int cc = e >> 3, k = e & 7;
            As[k][cc] = Vb[(size_t)(c0 + cc) * HWSZ + k0 + k];
        }
        #pragma unroll
        for (int j = 0; j < 4; ++j) {
            int e = tid * 4 + j;
            int mm = e >> 3, k = e & 7;
            Bs[k][mm] = Pb[(size_t)(m0 + mm) * HWSZ + k0 + k];
        }
        __syncthreads();
        #pragma unroll
        for (int k = 0; k < 8; ++k) {
            float a[8], bb[8];
            #pragma unroll
            for (int i = 0; i < 8; ++i) a[i]  = As[k][ty * 8 + i];
            #pragma unroll
            for (int j = 0; j < 8; ++j) bb[j] = Bs[k][tx * 8 + j];
            #pragma unroll
            for (int i = 0; i < 8; ++i)
                #pragma unroll
                for (int j = 0; j < 8; ++j)
                    acc[i][j] = fmaf(a[i], bb[j], acc[i][j]);
        }
        __syncthreads();
    }

    const float g = *gammap;
    #pragma unroll
    for (int i = 0; i < 8; ++i) {
        int c = c0 + ty * 8 + i;
        size_t base = ((size_t)(b * CCH + c)) * HWSZ;
        #pragma unroll
        for (int j = 0; j < 8; ++j) {
            int m = m0 + tx * 8 + j;
            out[base + m] = acc[i][j] * g + ref[base + m];
        }
    }
}

// ---------------------------------------------------------------------------
// Launch. Inputs (metadata order): inputs, ref, w1, w2, gamma.
// NOTE: the reference's conv on `inputs` is dead code (its result is
// overwritten before use), so `inputs` only contributes its shape — skipped.
// ---------------------------------------------------------------------------
extern "C" void kernel_launch(void* const* d_in, const int* in_sizes, int n_in,
                              void* d_out, int out_size)
{
    const float* ref   = (const float*)d_in[1];
    const float* w1    = (const float*)d_in[2];
    const float* w2    = (const float*)d_in[3];
    const float* gamma = (const float*)d_in[4];
    float* out = (float*)d_out;

    float* x1 = nullptr; cudaGetSymbolAddress((void**)&x1, g_x1);
    float* v  = nullptr; cudaGetSymbolAddress((void**)&v,  g_v);
    float* S  = nullptr; cudaGetSymbolAddress((void**)&S,  g_S);

    dim3 blk(256);

    // conv1 -> x1, conv2 -> v   (N = 16384 -> 128 tiles; M = 256 -> 2 tiles)
    conv_relu_kernel<<<dim3(128, 2), blk>>>(ref, w1, x1);
    conv_relu_kernel<<<dim3(128, 2), blk>>>(ref, w2, v);

    // S = X^T X  (per-batch 4096x4096, K=256)
    gram_kernel<<<dim3(32, 32, BATCH), blk>>>(x1, S);

    // row softmax in place (== corr^T by symmetry of S)
    softmax_kernel<<<dim3(HWSZ, BATCH), blk>>>(S);

    // out = gamma * (V @ P^T) + ref
    av_kernel<<<dim3(32, 2, BATCH), blk>>>(v, S, ref, gamma, out);
}

// round 2
// speedup vs baseline: 3.7041x; 3.7041x over previous
#include <cuda_runtime.h>
#include <cstdint>
#include <math_constants.h>

// Problem constants
constexpr int BATCH = 4;
constexpr int CCH   = 256;
constexpr int HH    = 64;
constexpr int WW    = 64;
constexpr int HWSZ  = HH * WW;   // 4096
constexpr int KCONV = CCH * 9;   // 2304

// Scratch (allocation-free rule: __device__ globals)
__device__ float g_x1[(size_t)BATCH * CCH * HWSZ];
__device__ float g_v [(size_t)BATCH * CCH * HWSZ];
__device__ float g_S [(size_t)BATCH * HWSZ * HWSZ];   // 268 MB

// ---------------------------------------------------------------------------
// helpers
// ---------------------------------------------------------------------------
__device__ __forceinline__ uint32_t su32(const void* p) {
    return (uint32_t)__cvta_generic_to_shared(p);
}
__device__ __forceinline__ void cp16(uint32_t d, const void* s) {
    asm volatile("cp.async.cg.shared.global [%0], [%1], 16;" :: "r"(d), "l"(s));
}
__device__ __forceinline__ void cp4(uint32_t d, const void* s, int sz) {
    asm volatile("cp.async.ca.shared.global [%0], [%1], 4, %2;" :: "r"(d), "l"(s), "r"(sz));
}
__device__ __forceinline__ void cpcommit() { asm volatile("cp.async.commit_group;"); }
template<int N> __device__ __forceinline__ void cpwait() {
    asm volatile("cp.async.wait_group %0;" :: "n"(N));
}
// D += A*B, m16n8k8 tf32 (fp32 regs, HW truncates mantissa)
__device__ __forceinline__ void mma8(float* c, const uint32_t* a, const uint32_t* b) {
    asm volatile(
        "mma.sync.aligned.m16n8k8.row.col.f32.tf32.tf32.f32 "
        "{%0,%1,%2,%3}, {%4,%5,%6,%7}, {%8,%9}, {%0,%1,%2,%3};"
        : "+f"(c[0]), "+f"(c[1]), "+f"(c[2]), "+f"(c[3])
        : "r"(a[0]), "r"(a[1]), "r"(a[2]), "r"(a[3]), "r"(b[0]), "r"(b[1]));
}
__device__ __forceinline__ float relu(float x) { return x > 0.f ? x : 0.f; }

// ===========================================================================
// Kernel 1: BOTH 3x3 SAME convs + ReLU, implicit GEMM on tensor cores.
//   M = 512 (256 ch of w1, 256 of w2), N = 16384 (b*HW), K = 2304.
//   128x128 CTA tile, warp 64x32, BK=16, PIPE=4 cp.async pipeline.
// ===========================================================================
constexpr int CONV_PIPE = 4;
constexpr int CONV_SMEM = (CONV_PIPE*128*20 + CONV_PIPE*16*132) * 4;

__global__ __launch_bounds__(256) void conv_mma(
    const float* __restrict__ in,    // ref [B,C,H,W]
    const float* __restrict__ w1, const float* __restrict__ w2,
    float* __restrict__ x1out, float* __restrict__ vout)
{
    extern __shared__ char dsm[];
    float (*Ws)[128][20] = (float(*)[128][20])dsm;                        // [pipe][m][k]
    float (*Bs)[16][132] = (float(*)[16][132])(dsm + CONV_PIPE*128*20*4); // [pipe][k][n]

    const int tid = threadIdx.x;
    const int lane = tid & 31, wid = tid >> 5;
    const int warp_r = wid >> 2, warp_c = wid & 3;   // 2 x 4 warp grid
    const int g = lane >> 2, t = lane & 3;
    const int n0 = blockIdx.x * 128;
    const int m0 = blockIdx.y * 128;                 // over 512

    // per-CTA: which conv
    const float* wbase = (m0 < 256) ? w1 : w2;
    float* obase       = (m0 < 256) ? x1out : vout;
    const int mrel0    = (m0 < 256) ? m0 : m0 - 256;

    // weight load slots (2 x 16B per thread per stage)
    int mA[2], kqA[2];
    const float* wrp[2];
    #pragma unroll
    for (int p = 0; p < 2; ++p) {
        int q = tid + 256 * p;
        mA[p]  = q >> 2;
        kqA[p] = (q & 3) * 4;
        wrp[p] = wbase + (size_t)(mrel0 + mA[p]) * KCONV;
    }
    // im2col: spatial position fixed per thread
    const int nl = tid & 127;
    const int nn = n0 + nl;
    const int bidx = nn >> 12, sp = nn & 4095;
    const int y0 = sp >> 6, x0 = sp & 63;
    const float* inb = in + (size_t)bidx * CCH * HWSZ;
    const int khalf = tid >> 7;

    float acc[4][4][4] = {};

    auto issue = [&](int ks, int bf) {
        #pragma unroll
        for (int p = 0; p < 2; ++p)
            cp16(su32(&Ws[bf][mA[p]][kqA[p]]), wrp[p] + ks * 16 + kqA[p]);
        #pragma unroll
        for (int r = 0; r < 8; ++r) {
            int kl = khalf + 2 * r;
            int kg = ks * 16 + kl;
            int ic = kg / 9;
            int rem = kg - ic * 9;
            int ky = rem / 3;
            int kx = rem - ky * 3;
            int yv = y0 + ky - 1, xv = x0 + kx - 1;
            bool ok = ((unsigned)yv < 64u) && ((unsigned)xv < 64u);
            const float* src = ok ? (inb + ((size_t)ic * 64 + yv) * 64 + xv) : in;
            cp4(su32(&Bs[bf][kl][nl]), src, ok ? 4 : 0);
        }
    };

    constexpr int STEPS = KCONV / 16;  // 144
    #pragma unroll
    for (int i = 0; i < CONV_PIPE - 1; ++i) { issue(i, i); cpcommit(); }

    for (int s = 0; s < STEPS; ++s) {
        cpwait<CONV_PIPE - 2>();
        __syncthreads();
        const int bf = s % CONV_PIPE;
        #pragma unroll
        for (int kk = 0; kk < 2; ++kk) {
            const int kb = kk * 8;
            uint32_t a[4][4], bfr[4][2];
            #pragma unroll
            for (int rt = 0; rt < 4; ++rt) {
                int rb = warp_r * 64 + rt * 16 + g;
                a[rt][0] = __float_as_uint(Ws[bf][rb    ][kb + t]);
                a[rt][1] = __float_as_uint(Ws[bf][rb + 8][kb + t]);
                a[rt][2] = __float_as_uint(Ws[bf][rb    ][kb + t + 4]);
                a[rt][3] = __float_as_uint(Ws[bf][rb + 8][kb + t + 4]);
            }
            #pragma unroll
            for (int ct = 0; ct < 4; ++ct) {
                int cb = warp_c * 32 + ct * 8 + g;
                bfr[ct][0] = __float_as_uint(Bs[bf][kb + t    ][cb]);
                bfr[ct][1] = __float_as_uint(Bs[bf][kb + t + 4][cb]);
            }
            #pragma unroll
            for (int rt = 0; rt < 4; ++rt)
                #pragma unroll
                for (int ct = 0; ct < 4; ++ct)
                    mma8(acc[rt][ct], a[rt], bfr[ct]);
        }
        int nx = s + CONV_PIPE - 1;
        if (nx < STEPS) issue(nx, nx % CONV_PIPE);
        cpcommit();
    }

    #pragma unroll
    for (int rt = 0; rt < 4; ++rt)
        #pragma unroll
        for (int ct = 0; ct < 4; ++ct) {
            int mch = mrel0 + warp_r * 64 + rt * 16 + g;
            int ng  = n0 + warp_c * 32 + ct * 8 + 2 * t;
            int b2  = ng >> 12, s2 = ng & 4095;
            float2 v0 = { relu(acc[rt][ct][0]), relu(acc[rt][ct][1]) };
            float2 v1 = { relu(acc[rt][ct][2]), relu(acc[rt][ct][3]) };
            *(float2*)(obase + ((size_t)(b2 * CCH + mch    )) * HWSZ + s2) = v0;
            *(float2*)(obase + ((size_t)(b2 * CCH + mch + 8)) * HWSZ + s2) = v1;
        }
}

// ===========================================================================
// Kernel 2: Gram S = X^T X per batch (4096x4096, K=256) on tensor cores.
// ===========================================================================
constexpr int GRAM_PIPE = 4;
constexpr int GRAM_SMEM = 2 * GRAM_PIPE * 16 * 136 * 4;

__global__ __launch_bounds__(256) void gram_mma(
    const float* __restrict__ X, float* __restrict__ S)
{
    extern __shared__ char dsm[];
    float (*An)[16][136] = (float(*)[16][136])dsm;                          // n-side [k][n]
    float (*Bm)[16][136] = (float(*)[16][136])(dsm + GRAM_PIPE*16*136*4);   // m-side [k][m]

    const int b = blockIdx.z;
    const float* Xb = X + (size_t)b * CCH * HWSZ;
    float* Sb = S + (size_t)b * HWSZ * HWSZ;

    const int tid = threadIdx.x;
    const int lane = tid & 31, wid = tid >> 5;
    const int warp_r = wid >> 2, warp_c = wid & 3;
    const int g = lane >> 2, t = lane & 3;
    const int m0 = blockIdx.x * 128;
    const int n0 = blockIdx.y * 128;

    float acc[4][4][4] = {};

    auto issue = [&](int ks, int bf) {
        #pragma unroll
        for (int p = 0; p < 2; ++p) {
            int q = tid + 256 * p;
            int kr = q >> 5;
            int nc = (q & 31) * 4;
            const float* row = Xb + (size_t)(ks * 16 + kr) * HWSZ;
            cp16(su32(&An[bf][kr][nc]), row + n0 + nc);
            cp16(su32(&Bm[bf][kr][nc]), row + m0 + nc);
        }
    };

    constexpr int STEPS = CCH / 16;  // 16
    #pragma unroll
    for (int i = 0; i < GRAM_PIPE - 1; ++i) { issue(i, i); cpcommit(); }

    for (int s = 0; s < STEPS; ++s) {
        cpwait<GRAM_PIPE - 2>();
        __syncthreads();
        const int bf = s % GRAM_PIPE;
        #pragma unroll
        for (int kk = 0; kk < 2; ++kk) {
            const int kb = kk * 8;
            uint32_t a[4][4], bfr[4][2];
            #pragma unroll
            for (int rt = 0; rt < 4; ++rt) {
                int rb = warp_r * 64 + rt * 16 + g;
                a[rt][0] = __float_as_uint(An[bf][kb + t    ][rb]);
                a[rt][1] = __float_as_uint(An[bf][kb + t    ][rb + 8]);
                a[rt][2] = __float_as_uint(An[bf][kb + t + 4][rb]);
                a[rt][3] = __float_as_uint(An[bf][kb + t + 4][rb + 8]);
            }
            #pragma unroll
            for (int ct = 0; ct < 4; ++ct) {
                int cb = warp_c * 32 + ct * 8 + g;
                bfr[ct][0] = __float_as_uint(Bm[bf][kb + t    ][cb]);
                bfr[ct][1] = __float_as_uint(Bm[bf][kb + t + 4][cb]);
            }
            #pragma unroll
            for (int rt = 0; rt < 4; ++rt)
                #pragma unroll
                for (int ct = 0; ct < 4; ++ct)
                    mma8(acc[rt][ct], a[rt], bfr[ct]);
        }
        int nx = s + GRAM_PIPE - 1;
        if (nx < STEPS) issue(nx, nx % GRAM_PIPE);
        cpcommit();
    }

    #pragma unroll
    for (int rt = 0; rt < 4; ++rt)
        #pragma unroll
        for (int ct = 0; ct < 4; ++ct) {
            int n = n0 + warp_r * 64 + rt * 16 + g;
            int m = m0 + warp_c * 32 + ct * 8 + 2 * t;
            *(float2*)(Sb + (size_t)n * HWSZ + m)       = make_float2(acc[rt][ct][0], acc[rt][ct][1]);
            *(float2*)(Sb + (size_t)(n + 8) * HWSZ + m) = make_float2(acc[rt][ct][2], acc[rt][ct][3]);
        }
}

// ===========================================================================
// Kernel 3: row softmax of S in place (S symmetric => row softmax == corr^T).
// ===========================================================================
__device__ __forceinline__ float warpMax(float v) {
    #pragma unroll
    for (int o = 16; o; o >>= 1) v = fmaxf(v, __shfl_xor_sync(0xffffffffu, v, o));
    return v;
}
__device__ __forceinline__ float warpSum(float v) {
    #pragma unroll
    for (int o = 16; o; o >>= 1) v += __shfl_xor_sync(0xffffffffu, v, o);
    return v;
}

__global__ __launch_bounds__(256) void softmax_kernel(float* __restrict__ S)
{
    float* p = S + (size_t)blockIdx.y * HWSZ * HWSZ + (size_t)blockIdx.x * HWSZ;
    const int tid = threadIdx.x;
    __shared__ float red[8];

    float vals[16];
    float mx = -CUDART_INF_F;
    #pragma unroll
    for (int i = 0; i < 16; ++i) {
        vals[i] = p[tid + i * 256];
        mx = fmaxf(mx, vals[i]);
    }
    mx = warpMax(mx);
    if ((tid & 31) == 0) red[tid >> 5] = mx;
    __syncthreads();
    {
        float m = red[tid & 7];
        #pragma unroll
        for (int o = 4; o; o >>= 1) m = fmaxf(m, __shfl_xor_sync(0xffffffffu, m, o));
        mx = m;
    }
    float sum = 0.f;
    #pragma unroll
    for (int i = 0; i < 16; ++i) {
        vals[i] = __expf(vals[i] - mx);
        sum += vals[i];
    }
    sum = warpSum(sum);
    __syncthreads();
    if ((tid & 31) == 0) red[tid >> 5] = sum;
    __syncthreads();
    {
        float s = red[tid & 7];
        #pragma unroll
        for (int o = 4; o; o >>= 1) s += __shfl_xor_sync(0xffffffffu, s, o);
        sum = s;
    }
    float inv = 1.f / sum;
    #pragma unroll
    for (int i = 0; i < 16; ++i)
        p[tid + i * 256] = vals[i] * inv;
}

// ===========================================================================
// Kernel 4: A = V * P^T per batch (256 x 4096, K=4096), fused
//           out = gamma*A + ref.  BK=32, PIPE=3.
// ===========================================================================
constexpr int AV_PIPE = 3;
constexpr int AV_SMEM = 2 * AV_PIPE * 128 * 36 * 4;

__global__ __launch_bounds__(256) void av_mma(
    const float* __restrict__ V, const float* __restrict__ P,
    const float* __restrict__ ref, const float* __restrict__ gammap,
    float* __restrict__ out)
{
    extern __shared__ char dsm[];
    float (*Vs)[128][36] = (float(*)[128][36])dsm;                       // [c][k]
    float (*Ps)[128][36] = (float(*)[128][36])(dsm + AV_PIPE*128*36*4);  // [m][k]

    const int b = blockIdx.z;
    const float* Vb = V + (size_t)b * CCH * HWSZ;
    const float* Pb = P + (size_t)b * HWSZ * HWSZ;

    const int tid = threadIdx.x;
    const int lane = tid & 31, wid = tid >> 5;
    const int warp_r = wid >> 2, warp_c = wid & 3;
    const int g = lane >> 2, t = lane & 3;
    const int m0 = blockIdx.x * 128;
    const int c0 = blockIdx.y * 128;

    float acc[4][4][4] = {};

    auto issue = [&](int ks, int bf) {
        #pragma unroll
        for (int p = 0; p < 4; ++p) {
            int q = tid + 256 * p;
            int row = q >> 3;
            int kq  = (q & 7) * 4;
            cp16(su32(&Vs[bf][row][kq]), Vb + (size_t)(c0 + row) * HWSZ + ks * 32 + kq);
            cp16(su32(&Ps[bf][row][kq]), Pb + (size_t)(m0 + row) * HWSZ + ks * 32 + kq);
        }
    };

    constexpr int STEPS = HWSZ / 32;  // 128
    #pragma unroll
    for (int i = 0; i < AV_PIPE - 1; ++i) { issue(i, i); cpcommit(); }

    for (int s = 0; s < STEPS; ++s) {
        cpwait<AV_PIPE - 2>();
        __syncthreads();
        const int bf = s % AV_PIPE;
        #pragma unroll
        for (int kk = 0; kk < 4; ++kk) {
            const int kb = kk * 8;
            uint32_t a[4][4], bfr[4][2];
            #pragma unroll
            for (int rt = 0; rt < 4; ++rt) {
                int rb = warp_r * 64 + rt * 16 + g;
                a[rt][0] = __float_as_uint(Vs[bf][rb    ][kb + t]);
                a[rt][1] = __float_as_uint(Vs[bf][rb + 8][kb + t]);
                a[rt][2] = __float_as_uint(Vs[bf][rb    ][kb + t + 4]);
                a[rt][3] = __float_as_uint(Vs[bf][rb + 8][kb + t + 4]);
            }
            #pragma unroll
            for (int ct = 0; ct < 4; ++ct) {
                int cb = warp_c * 32 + ct * 8 + g;
                bfr[ct][0] = __float_as_uint(Ps[bf][cb][kb + t]);
                bfr[ct][1] = __float_as_uint(Ps[bf][cb][kb + t + 4]);
            }
            #pragma unroll
            for (int rt = 0; rt < 4; ++rt)
                #pragma unroll
                for (int ct = 0; ct < 4; ++ct)
                    mma8(acc[rt][ct], a[rt], bfr[ct]);
        }
        int nx = s + AV_PIPE - 1;
        if (nx < STEPS) issue(nx, nx % AV_PIPE);
        cpcommit();
    }

    const float gm = *gammap;
    #pragma unroll
    for (int rt = 0; rt < 4; ++rt)
        #pragma unroll
        for (int ct = 0; ct < 4; ++ct) {
            int c = c0 + warp_r * 64 + rt * 16 + g;
            int m = m0 + warp_c * 32 + ct * 8 + 2 * t;
            size_t a0 = ((size_t)(b * CCH + c)) * HWSZ + m;
            size_t a1 = ((size_t)(b * CCH + c + 8)) * HWSZ + m;
            float2 r0 = *(const float2*)(ref + a0);
            float2 r1 = *(const float2*)(ref + a1);
            float2 o0 = { acc[rt][ct][0] * gm + r0.x, acc[rt][ct][1] * gm + r0.y };
            float2 o1 = { acc[rt][ct][2] * gm + r1.x, acc[rt][ct][3] * gm + r1.y };
            *(float2*)(out + a0) = o0;
            *(float2*)(out + a1) = o1;
        }
}

// ---------------------------------------------------------------------------
// Launch. Inputs: inputs, ref, w1, w2, gamma. (conv on `inputs` is dead code)
// ---------------------------------------------------------------------------
extern "C" void kernel_launch(void* const* d_in, const int* in_sizes, int n_in,
                              void* d_out, int out_size)
{
    const float* ref   = (const float*)d_in[1];
    const float* w1    = (const float*)d_in[2];
    const float* w2    = (const float*)d_in[3];
    const float* gamma = (const float*)d_in[4];
    float* out = (float*)d_out;

    float* x1 = nullptr; cudaGetSymbolAddress((void**)&x1, g_x1);
    float* v  = nullptr; cudaGetSymbolAddress((void**)&v,  g_v);
    float* S  = nullptr; cudaGetSymbolAddress((void**)&S,  g_S);

    cudaFuncSetAttribute(conv_mma, cudaFuncAttributeMaxDynamicSharedMemorySize, CONV_SMEM);
    cudaFuncSetAttribute(gram_mma, cudaFuncAttributeMaxDynamicSharedMemorySize, GRAM_SMEM);
    cudaFuncSetAttribute(av_mma,   cudaFuncAttributeMaxDynamicSharedMemorySize, AV_SMEM);

    conv_mma<<<dim3(128, 4), 256, CONV_SMEM>>>(ref, w1, w2, x1, v);
    gram_mma<<<dim3(32, 32, BATCH), 256, GRAM_SMEM>>>(x1, S);
    softmax_kernel<<<dim3(HWSZ, BATCH), 256>>>(S);
    av_mma<<<dim3(32, 2, BATCH), 256, AV_SMEM>>>(v, S, ref, gamma, out);
}

// round 5
// speedup vs baseline: 5.7982x; 1.5653x over previous
#include <cuda_runtime.h>
#include <cuda_fp16.h>
#include <cstdint>
#include <math_constants.h>

constexpr int BATCH = 4;
constexpr int CCH   = 256;
constexpr int HH    = 64;
constexpr int WW    = 64;
constexpr int HWSZ  = HH * WW;   // 4096
constexpr int KCONV = CCH * 9;   // 2304

// Scratch (__device__ globals: allocation-free rule)
__device__ __half g_x1t[(size_t)BATCH * HWSZ * CCH];   // relu(conv1) transposed [B,HW,C] fp16
__device__ __half g_vh [(size_t)BATCH * CCH * HWSZ];   // relu(conv2) [B,C,HW] fp16
__device__ float  g_S  [(size_t)BATCH * HWSZ * HWSZ];  // scores fp32 (268 MB)
__device__ __half g_P  [(size_t)BATCH * HWSZ * HWSZ];  // softmax rows fp16 (134 MB)

// ---------------------------------------------------------------------------
// helpers
// ---------------------------------------------------------------------------
__device__ __forceinline__ uint32_t su32(const void* p) {
    return (uint32_t)__cvta_generic_to_shared(p);
}
__device__ __forceinline__ void cp16(uint32_t d, const void* s) {
    asm volatile("cp.async.cg.shared.global [%0], [%1], 16;" :: "r"(d), "l"(s));
}
__device__ __forceinline__ void cpcommit() { asm volatile("cp.async.commit_group;"); }
template<int N> __device__ __forceinline__ void cpwait() {
    asm volatile("cp.async.wait_group %0;" :: "n"(N));
}
__device__ __forceinline__ void mma16(float* c, const uint32_t* a, const uint32_t* b) {
    asm volatile(
        "mma.sync.aligned.m16n8k16.row.col.f32.f16.f16.f32 "
        "{%0,%1,%2,%3}, {%4,%5,%6,%7}, {%8,%9}, {%0,%1,%2,%3};"
        : "+f"(c[0]), "+f"(c[1]), "+f"(c[2]), "+f"(c[3])
        : "r"(a[0]), "r"(a[1]), "r"(a[2]), "r"(a[3]), "r"(b[0]), "r"(b[1]));
}
__device__ __forceinline__ void ldsm4(uint32_t& r0, uint32_t& r1, uint32_t& r2, uint32_t& r3, uint32_t a) {
    asm volatile("ldmatrix.sync.aligned.m8n8.x4.shared.b16 {%0,%1,%2,%3}, [%4];"
        : "=r"(r0), "=r"(r1), "=r"(r2), "=r"(r3) : "r"(a));
}
__device__ __forceinline__ void ldsm4t(uint32_t& r0, uint32_t& r1, uint32_t& r2, uint32_t& r3, uint32_t a) {
    asm volatile("ldmatrix.sync.aligned.m8n8.x4.trans.shared.b16 {%0,%1,%2,%3}, [%4];"
        : "=r"(r0), "=r"(r1), "=r"(r2), "=r"(r3) : "r"(a));
}
__device__ __forceinline__ float relu(float x) { return x > 0.f ? x : 0.f; }
__device__ __forceinline__ uint32_t pack2(float lo, float hi) {
    __half2 h = __floats2half2_rn(lo, hi);
    return *(uint32_t*)&h;
}

// ===========================================================================
// Kernel 1: BOTH 3x3 convs + ReLU, implicit GEMM, fp16 mma m16n8k16.
//   M = 512 (256ch w1 | 256ch w2), N = 16384, K = 2304, BK=16.
//   Synchronous reg double-buffer (gmem fp32 -> cvt fp16 -> smem).
// ===========================================================================
__global__ __launch_bounds__(256) void conv_mma(
    const float* __restrict__ in, const float* __restrict__ w1,
    const float* __restrict__ w2,
    __half* __restrict__ x1t, __half* __restrict__ vout)
{
    __shared__ __half Ws[2][128][24];   // [m][k], row 48B
    __shared__ __half Bs[2][16][136];   // [k][n], row 272B

    const int tid = threadIdx.x, lane = tid & 31, wid = tid >> 5;
    const int warp_r = wid >> 2, warp_c = wid & 3;
    const int g = lane >> 2, t = lane & 3;
    const int n0 = blockIdx.x * 128, m0 = blockIdx.y * 128;

    const float* wbase = (m0 < 256) ? w1 : w2;
    const int mrel0 = (m0 < 256) ? m0 : m0 - 256;

    // weight loader mapping: thread -> (m row, k-octet)
    const int wm = tid >> 1, wk8 = (tid & 1) * 8;
    const float* wrow = wbase + (size_t)(mrel0 + wm) * KCONV + wk8;
    // im2col mapping: thread -> n column, 8 k rows
    const int nl = tid & 127;
    const int nn = n0 + nl;
    const int bidx = nn >> 12, sp = nn & 4095;
    const int y0 = sp >> 6, x0 = sp & 63;
    const float* inb = in + (size_t)bidx * CCH * HWSZ;
    const int khalf = tid >> 7;

    float acc[4][4][4] = {};
    float4 wv0, wv1;
    float bvf[8];

    auto loadRegs = [&](int ks) {
        const float* wp = wrow + ks * 16;
        wv0 = *(const float4*)wp;
        wv1 = *(const float4*)(wp + 4);
        #pragma unroll
        for (int r = 0; r < 8; ++r) {
            int kg = ks * 16 + khalf + 2 * r;
            int ic = kg / 9;
            int rem = kg - ic * 9;
            int ky = rem / 3;
            int kx = rem - 3 * ky;
            int yv = y0 + ky - 1, xv = x0 + kx - 1;
            bool ok = ((unsigned)yv < 64u) && ((unsigned)xv < 64u);
            bvf[r] = ok ? inb[((size_t)ic << 12) + (yv << 6) + xv] : 0.f;
        }
    };
    auto storeRegs = [&](int buf) {
        uint4 wp;
        wp.x = pack2(wv0.x, wv0.y); wp.y = pack2(wv0.z, wv0.w);
        wp.z = pack2(wv1.x, wv1.y); wp.w = pack2(wv1.z, wv1.w);
        *(uint4*)&Ws[buf][wm][wk8] = wp;
        #pragma unroll
        for (int r = 0; r < 8; ++r)
            Bs[buf][khalf + 2 * r][nl] = __float2half(bvf[r]);
    };

    const int l15 = lane & 15, lhi = (lane >> 4) * 8;
    const uint32_t aAddr = su32(&Ws[0][warp_r * 64 + l15][lhi]);
    const uint32_t bAddr = su32(&Bs[0][l15][warp_c * 32 + lhi]);
    constexpr int WsBuf = 128 * 24 * 2;
    constexpr int BsBuf = 16 * 136 * 2;
    constexpr int WsRow = 24 * 2;

    auto compute = [&](int buf) {
        uint32_t a[4][4], bq[2][4];
        #pragma unroll
        for (int rt = 0; rt < 4; ++rt)
            ldsm4(a[rt][0], a[rt][1], a[rt][2], a[rt][3],
                  aAddr + buf * WsBuf + rt * 16 * WsRow);
        #pragma unroll
        for (int cp = 0; cp < 2; ++cp)
            ldsm4t(bq[cp][0], bq[cp][1], bq[cp][2], bq[cp][3],
                   bAddr + buf * BsBuf + cp * 16 * 2);
        #pragma unroll
        for (int rt = 0; rt < 4; ++rt)
            #pragma unroll
            for (int cp = 0; cp < 2; ++cp) {
                mma16(acc[rt][cp * 2],     a[rt], &bq[cp][0]);
                mma16(acc[rt][cp * 2 + 1], a[rt], &bq[cp][2]);
            }
    };

    constexpr int STEPS = KCONV / 16;   // 144
    loadRegs(0);
    storeRegs(0);
    loadRegs(1);
    for (int s = 0; s < STEPS; ++s) {
        __syncthreads();
        int cur = s & 1;
        if (s + 1 < STEPS) storeRegs(cur ^ 1);
        if (s + 2 < STEPS) loadRegs(s + 2);
        compute(cur);
    }

    if (m0 < 256) {
        // x1 -> transposed fp16 [B][HW][C]
        #pragma unroll
        for (int rt = 0; rt < 4; ++rt)
            #pragma unroll
            for (int ct = 0; ct < 4; ++ct) {
                int c = mrel0 + warp_r * 64 + rt * 16 + g;
                int n = n0 + warp_c * 32 + ct * 8 + 2 * t;
                int b2 = n >> 12, s2 = n & 4095;
                size_t base = ((size_t)b2 * HWSZ + s2) * CCH;
                x1t[base + c]           = __float2half(relu(acc[rt][ct][0]));
                x1t[base + CCH + c]     = __float2half(relu(acc[rt][ct][1]));
                x1t[base + c + 8]       = __float2half(relu(acc[rt][ct][2]));
                x1t[base + CCH + c + 8] = __float2half(relu(acc[rt][ct][3]));
            }
    } else {
        // v -> fp16 [B][C][HW]
        #pragma unroll
        for (int rt = 0; rt < 4; ++rt)
            #pragma unroll
            for (int ct = 0; ct < 4; ++ct) {
                int c = mrel0 + warp_r * 64 + rt * 16 + g;
                int n = n0 + warp_c * 32 + ct * 8 + 2 * t;
                int b2 = n >> 12, s2 = n & 4095;
                *(uint32_t*)&vout[((size_t)(b2 * CCH + c)) * HWSZ + s2] =
                    pack2(relu(acc[rt][ct][0]), relu(acc[rt][ct][1]));
                *(uint32_t*)&vout[((size_t)(b2 * CCH + c + 8)) * HWSZ + s2] =
                    pack2(relu(acc[rt][ct][2]), relu(acc[rt][ct][3]));
            }
    }
}

// ===========================================================================
// Kernel 2: Gram S = Xt Xt^T per batch (4096x4096, K=256), fp16 in, fp32 out.
//   BK=32, PIPE=3, cp.async, ldmatrix non-trans both sides (Xt is [n][c]).
// ===========================================================================
constexpr int GP = 3;
constexpr int G_TILE = 128 * 40;                // halves per tile per stage
constexpr int GRAM_SMEM = GP * 2 * G_TILE * 2;  // 61440 B

__global__ __launch_bounds__(256) void gram_mma(
    const __half* __restrict__ Xt, float* __restrict__ S)
{
    extern __shared__ __half sh[];
    __half* An = sh;                 // [GP][128][40]  (n rows)
    __half* Bm = sh + GP * G_TILE;   // [GP][128][40]  (m rows)

    const int b = blockIdx.z;
    const __half* xb = Xt + (size_t)b * HWSZ * CCH;
    float* Sb = S + (size_t)b * HWSZ * HWSZ;

    const int tid = threadIdx.x, lane = tid & 31, wid = tid >> 5;
    const int warp_r = wid >> 2, warp_c = wid & 3;
    const int g = lane >> 2, t = lane & 3;
    const int m0 = blockIdx.x * 128, n0 = blockIdx.y * 128;

    float acc[4][4][4] = {};

    auto issue = [&](int ks, int bf) {
        #pragma unroll
        for (int j = 0; j < 2; ++j) {
            int e = tid + 256 * j;
            int row = e >> 2, kq = (e & 3) * 8;
            cp16(su32(An + bf * G_TILE + row * 40 + kq),
                 xb + (size_t)(n0 + row) * CCH + ks * 32 + kq);
            cp16(su32(Bm + bf * G_TILE + row * 40 + kq),
                 xb + (size_t)(m0 + row) * CCH + ks * 32 + kq);
        }
    };

    const int l15 = lane & 15, lhi = (lane >> 4) * 8;
    const int mof = ((lane >> 4) & 1) * 8 + (lane & 7);
    const int kof = ((lane >> 3) & 1) * 8;
    const uint32_t aBase = su32(An + (warp_r * 64 + l15) * 40 + lhi);
    const uint32_t bBase = su32(Bm + (warp_c * 32 + mof) * 40 + kof);
    constexpr int BUFB = G_TILE * 2;

    constexpr int STEPS = CCH / 32;  // 8
    #pragma unroll
    for (int i = 0; i < GP - 1; ++i) { issue(i, i); cpcommit(); }

    for (int s = 0; s < STEPS; ++s) {
        cpwait<GP - 2>();
        __syncthreads();
        const int bf = s % GP;
        #pragma unroll
        for (int kk = 0; kk < 2; ++kk) {
            uint32_t a[4][4], bq[2][4];
            #pragma unroll
            for (int rt = 0; rt < 4; ++rt)
                ldsm4(a[rt][0], a[rt][1], a[rt][2], a[rt][3],
                      aBase + bf * BUFB + rt * 16 * 80 + kk * 32);
            #pragma unroll
            for (int cp = 0; cp < 2; ++cp)
                ldsm4(bq[cp][0], bq[cp][1], bq[cp][2], bq[cp][3],
                      bBase + bf * BUFB + cp * 16 * 80 + kk * 32);
            #pragma unroll
            for (int rt = 0; rt < 4; ++rt)
                #pragma unroll
                for (int cp = 0; cp < 2; ++cp) {
                    mma16(acc[rt][cp * 2],     a[rt], &bq[cp][0]);
                    mma16(acc[rt][cp * 2 + 1], a[rt], &bq[cp][2]);
                }
        }
        int nx = s + GP - 1;
        if (nx < STEPS) issue(nx, nx % GP);
        cpcommit();
    }

    #pragma unroll
    for (int rt = 0; rt < 4; ++rt)
        #pragma unroll
        for (int ct = 0; ct < 4; ++ct) {
            int n = n0 + warp_r * 64 + rt * 16 + g;
            int m = m0 + warp_c * 32 + ct * 8 + 2 * t;
            *(float2*)(Sb + (size_t)n * HWSZ + m) =
                make_float2(acc[rt][ct][0], acc[rt][ct][1]);
            *(float2*)(Sb + (size_t)(n + 8) * HWSZ + m) =
                make_float2(acc[rt][ct][2], acc[rt][ct][3]);
        }
}

// ===========================================================================
// Kernel 3: row softmax of S (fp32 in), fp16 P out.
// ===========================================================================
__device__ __forceinline__ float warpMax(float v) {
    #pragma unroll
    for (int o = 16; o; o >>= 1) v = fmaxf(v, __shfl_xor_sync(0xffffffffu, v, o));
    return v;
}
__device__ __forceinline__ float warpSum(float v) {
    #pragma unroll
    for (int o = 16; o; o >>= 1) v += __shfl_xor_sync(0xffffffffu, v, o);
    return v;
}

__global__ __launch_bounds__(256) void softmax_kernel(
    const float* __restrict__ S, __half* __restrict__ P)
{
    const size_t roff = (size_t)blockIdx.y * HWSZ * HWSZ + (size_t)blockIdx.x * HWSZ;
    const float* p = S + roff;
    __half* q = P + roff;
    const int tid = threadIdx.x;
    __shared__ float red[8];

    float vals[16];
    float mx = -CUDART_INF_F;
    #pragma unroll
    for (int i = 0; i < 16; ++i) {
        vals[i] = p[tid + i * 256];
        mx = fmaxf(mx, vals[i]);
    }
    mx = warpMax(mx);
    if ((tid & 31) == 0) red[tid >> 5] = mx;
    __syncthreads();
    {
        float m = red[tid & 7];
        #pragma unroll
        for (int o = 4; o; o >>= 1) m = fmaxf(m, __shfl_xor_sync(0xffffffffu, m, o));
        mx = m;
    }
    float sum = 0.f;
    #pragma unroll
    for (int i = 0; i < 16; ++i) {
        vals[i] = __expf(vals[i] - mx);
        sum += vals[i];
    }
    sum = warpSum(sum);
    __syncthreads();
    if ((tid & 31) == 0) red[tid >> 5] = sum;
    __syncthreads();
    {
        float s = red[tid & 7];
        #pragma unroll
        for (int o = 4; o; o >>= 1) s += __shfl_xor_sync(0xffffffffu, s, o);
        sum = s;
    }
    float inv = 1.f / sum;
    #pragma unroll
    for (int i = 0; i < 16; ++i)
        q[tid + i * 256] = __float2half(vals[i] * inv);
}

// ===========================================================================
// Kernel 4: A = V P^T (256 x 4096, K=4096) fp16, epilogue out = gamma*A + ref.
// ===========================================================================
constexpr int AV_SMEM = GRAM_SMEM;

__global__ __launch_bounds__(256) void av_mma(
    const __half* __restrict__ V, const __half* __restrict__ P,
    const float* __restrict__ ref, const float* __restrict__ gammap,
    float* __restrict__ out)
{
    extern __shared__ __half sh[];
    __half* Vs = sh;                 // [GP][128 c][40]
    __half* Ps = sh + GP * G_TILE;   // [GP][128 m][40]

    const int b = blockIdx.z;
    const __half* vb = V + (size_t)b * CCH * HWSZ;
    const __half* pb = P + (size_t)b * HWSZ * HWSZ;

    const int tid = threadIdx.x, lane = tid & 31, wid = tid >> 5;
    const int warp_r = wid >> 2, warp_c = wid & 3;
    const int g = lane >> 2, t = lane & 3;
    const int m0 = blockIdx.x * 128, c0 = blockIdx.y * 128;

    float acc[4][4][4] = {};

    auto issue = [&](int ks, int bf) {
        #pragma unroll
        for (int j = 0; j < 2; ++j) {
            int e = tid + 256 * j;
            int row = e >> 2, kq = (e & 3) * 8;
            cp16(su32(Vs + bf * G_TILE + row * 40 + kq),
                 vb + (size_t)(c0 + row) * HWSZ + ks * 32 + kq);
            cp16(su32(Ps + bf * G_TILE + row * 40 + kq),
                 pb + (size_t)(m0 + row) * HWSZ + ks * 32 + kq);
        }
    };

    const int l15 = lane & 15, lhi = (lane >> 4) * 8;
    const int mof = ((lane >> 4) & 1) * 8 + (lane & 7);
    const int kof = ((lane >> 3) & 1) * 8;
    const uint32_t aBase = su32(Vs + (warp_r * 64 + l15) * 40 + lhi);
    const uint32_t bBase = su32(Ps + (warp_c * 32 + mof) * 40 + kof);
    constexpr int BUFB = G_TILE * 2;

    constexpr int STEPS = HWSZ / 32;  // 128
    #pragma unroll
    for (int i = 0; i < GP - 1; ++i) { issue(i, i); cpcommit(); }

    for (int s = 0; s < STEPS; ++s) {
        cpwait<GP - 2>();
        __syncthreads();
        const int bf = s % GP;
        #pragma unroll
        for (int kk = 0; kk < 2; ++kk) {
            uint32_t a[4][4], bq[2][4];
            #pragma unroll
            for (int rt = 0; rt < 4; ++rt)
                ldsm4(a[rt][0], a[rt][1], a[rt][2], a[rt][3],
                      aBase + bf * BUFB + rt * 16 * 80 + kk * 32);
            #pragma unroll
            for (int cp = 0; cp < 2; ++cp)
                ldsm4(bq[cp][0], bq[cp][1], bq[cp][2], bq[cp][3],
                      bBase + bf * BUFB + cp * 16 * 80 + kk * 32);
            #pragma unroll
            for (int rt = 0; rt < 4; ++rt)
                #pragma unroll
                for (int cp = 0; cp < 2; ++cp) {
                    mma16(acc[rt][cp * 2],     a[rt], &bq[cp][0]);
                    mma16(acc[rt][cp * 2 + 1], a[rt], &bq[cp][2]);
                }
        }
        int nx = s + GP - 1;
        if (nx < STEPS) issue(nx, nx % GP);
        cpcommit();
    }

    const float gm = *gammap;
    #pragma unroll
    for (int rt = 0; rt < 4; ++rt)
        #pragma unroll
        for (int ct = 0; ct < 4; ++ct) {
            int c = c0 + warp_r * 64 + rt * 16 + g;
            int m = m0 + warp_c * 32 + ct * 8 + 2 * t;
            size_t a0 = ((size_t)(b * CCH + c)) * HWSZ + m;
            size_t a1 = ((size_t)(b * CCH + c + 8)) * HWSZ + m;
            float2 r0 = *(const float2*)(ref + a0);
            float2 r1 = *(const float2*)(ref + a1);
            *(float2*)(out + a0) = make_float2(acc[rt][ct][0] * gm + r0.x,
                                               acc[rt][ct][1] * gm + r0.y);
            *(float2*)(out + a1) = make_float2(acc[rt][ct][2] * gm + r1.x,
                                               acc[rt][ct][3] * gm + r1.y);
        }
}

// ---------------------------------------------------------------------------
// Launch. Inputs: inputs, ref, w1, w2, gamma. (conv on `inputs` is dead code.)
// ---------------------------------------------------------------------------
extern "C" void kernel_launch(void* const* d_in, const int* in_sizes, int n_in,
                              void* d_out, int out_size)
{
    const float* ref   = (const float*)d_in[1];
    const float* w1    = (const float*)d_in[2];
    const float* w2    = (const float*)d_in[3];
    const float* gamma = (const float*)d_in[4];
    float* out = (float*)d_out;

    __half* x1t = nullptr; cudaGetSymbolAddress((void**)&x1t, g_x1t);
    __half* vh  = nullptr; cudaGetSymbolAddress((void**)&vh,  g_vh);
    float*  S   = nullptr; cudaGetSymbolAddress((void**)&S,   g_S);
    __half* P   = nullptr; cudaGetSymbolAddress((void**)&P,   g_P);

    cudaFuncSetAttribute(gram_mma, cudaFuncAttributeMaxDynamicSharedMemorySize, GRAM_SMEM);
    cudaFuncSetAttribute(av_mma,   cudaFuncAttributeMaxDynamicSharedMemorySize, AV_SMEM);

    conv_mma<<<dim3(128, 4), 256>>>(ref, w1, w2, x1t, vh);
    gram_mma<<<dim3(32, 32, BATCH), 256, GRAM_SMEM>>>(x1t, S);
    softmax_kernel<<<dim3(HWSZ, BATCH), 256>>>(S, P);
    av_mma<<<dim3(32, 2, BATCH), 256, AV_SMEM>>>(vh, P, ref, gamma, out);
}

// round 6
// speedup vs baseline: 7.0080x; 1.2086x over previous
#include <cuda_runtime.h>
#include <cuda_fp16.h>
#include <cstdint>
#include <math_constants.h>

constexpr int BATCH = 4;
constexpr int CCH   = 256;
constexpr int HH    = 64;
constexpr int WW    = 64;
constexpr int HWSZ  = HH * WW;   // 4096
constexpr int KCONV = CCH * 9;   // 2304

// Scratch (__device__ globals: allocation-free rule)
__device__ __half g_reft[(size_t)BATCH * HWSZ * CCH];  // ref transposed fp16 [B,HW,C]
__device__ __half g_wr  [(size_t)512 * KCONV];         // both conv weights, tap-major fp16
__device__ __half g_x1t [(size_t)BATCH * HWSZ * CCH];  // relu(conv1) [B,HW,C] fp16
__device__ __half g_vh  [(size_t)BATCH * CCH * HWSZ];  // relu(conv2) [B,C,HW] fp16
__device__ float  g_S   [(size_t)BATCH * HWSZ * HWSZ]; // scores fp32 (268 MB)
__device__ __half g_P   [(size_t)BATCH * HWSZ * HWSZ]; // softmax rows fp16 (134 MB)

// ---------------------------------------------------------------------------
// helpers
// ---------------------------------------------------------------------------
__device__ __forceinline__ uint32_t su32(const void* p) {
    return (uint32_t)__cvta_generic_to_shared(p);
}
__device__ __forceinline__ void cp16(uint32_t d, const void* s) {
    asm volatile("cp.async.cg.shared.global [%0], [%1], 16;" :: "r"(d), "l"(s));
}
__device__ __forceinline__ void cp16p(uint32_t d, const void* s, int sz) {
    asm volatile("cp.async.cg.shared.global [%0], [%1], 16, %2;" :: "r"(d), "l"(s), "r"(sz));
}
__device__ __forceinline__ void cpcommit() { asm volatile("cp.async.commit_group;"); }
template<int N> __device__ __forceinline__ void cpwait() {
    asm volatile("cp.async.wait_group %0;" :: "n"(N));
}
__device__ __forceinline__ void mma16(float* c, const uint32_t* a, const uint32_t* b) {
    asm volatile(
        "mma.sync.aligned.m16n8k16.row.col.f32.f16.f16.f32 "
        "{%0,%1,%2,%3}, {%4,%5,%6,%7}, {%8,%9}, {%0,%1,%2,%3};"
        : "+f"(c[0]), "+f"(c[1]), "+f"(c[2]), "+f"(c[3])
        : "r"(a[0]), "r"(a[1]), "r"(a[2]), "r"(a[3]), "r"(b[0]), "r"(b[1]));
}
__device__ __forceinline__ void ldsm4(uint32_t& r0, uint32_t& r1, uint32_t& r2, uint32_t& r3, uint32_t a) {
    asm volatile("ldmatrix.sync.aligned.m8n8.x4.shared.b16 {%0,%1,%2,%3}, [%4];"
        : "=r"(r0), "=r"(r1), "=r"(r2), "=r"(r3) : "r"(a));
}
__device__ __forceinline__ float relu(float x) { return x > 0.f ? x : 0.f; }
__device__ __forceinline__ uint32_t pack2(float lo, float hi) {
    __half2 h = __floats2half2_rn(lo, hi);
    return *(uint32_t*)&h;
}

// ===========================================================================
// Prep A: transpose ref fp32 [B,C,HW] -> fp16 [B,HW,C]
// ===========================================================================
__global__ __launch_bounds__(256) void transpose_ref(
    const float* __restrict__ in, __half* __restrict__ out)
{
    __shared__ float tile[32][33];
    const int b = blockIdx.z;
    const int s0 = blockIdx.x * 32, c0 = blockIdx.y * 32;
    const int tx = threadIdx.x & 31, ty = threadIdx.x >> 5;   // 32 x 8
    const float* ib = in + (size_t)b * CCH * HWSZ;
    #pragma unroll
    for (int i = 0; i < 4; ++i)
        tile[ty + i * 8][tx] = ib[(size_t)(c0 + ty + i * 8) * HWSZ + s0 + tx];
    __syncthreads();
    __half* ob = out + (size_t)b * HWSZ * CCH;
    #pragma unroll
    for (int i = 0; i < 4; ++i)
        ob[(size_t)(s0 + ty + i * 8) * CCH + c0 + tx] = __float2half(tile[tx][ty + i * 8]);
}

// ===========================================================================
// Prep B: reorder weights to tap-major fp16.  wr[o][tap*256+ic] = w[o][ic*9+tap]
//   o in [0,512): first 256 rows from w1, rest from w2.
// ===========================================================================
__global__ __launch_bounds__(256) void reorder_w(
    const float* __restrict__ w1, const float* __restrict__ w2,
    __half* __restrict__ wr)
{
    __shared__ float buf[KCONV];
    const int o = blockIdx.x;
    const float* src = (o < 256) ? (w1 + (size_t)o * KCONV)
                                 : (w2 + (size_t)(o - 256) * KCONV);
    for (int i = threadIdx.x; i < KCONV; i += 256) buf[i] = src[i];
    __syncthreads();
    __half* dst = wr + (size_t)o * KCONV;
    for (int j = threadIdx.x; j < KCONV; j += 256) {
        int ic = j & 255, tap = j >> 8;
        dst[j] = __float2half(buf[ic * 9 + tap]);
    }
}

// ===========================================================================
// Kernel 1: BOTH 3x3 convs + ReLU, implicit GEMM, fp16, tap-major K.
//   M=512, N=16384, K=2304 (k = tap*256+ic). BK=16 => one tap per step.
//   cp.async PIPE=4; B-tile rows are channel-contiguous in g_reft.
// ===========================================================================
constexpr int CPIPE = 4;
constexpr int CSTG  = 128 * 24;                 // halves per stage per array
constexpr int CONV_SMEM = CPIPE * 2 * CSTG * 2; // 49152 B

__global__ __launch_bounds__(256) void conv_mma(
    const __half* __restrict__ reft,   // [B,HW,C]
    const __half* __restrict__ wr,     // [512][2304] tap-major
    __half* __restrict__ x1t, __half* __restrict__ vout)
{
    extern __shared__ __half sh[];
    __half* Wsm = sh;                  // [CPIPE][128 m][24]
    __half* Bsm = sh + CPIPE * CSTG;   // [CPIPE][128 n][24]

    const int tid = threadIdx.x, lane = tid & 31, wid = tid >> 5;
    const int warp_r = wid >> 2, warp_c = wid & 3;
    const int g = lane >> 2, t = lane & 3;
    const int n0 = blockIdx.x * 128, m0 = blockIdx.y * 128;

    // weight loader: thread -> (m row, k-octet); 1 cp16 per step
    const int wm = tid >> 1, wk8 = (tid & 1) * 8;
    const __half* wrow = wr + (size_t)(m0 + wm) * KCONV + wk8;

    // B loader: thread -> (n col, k-octet); 1 predicated cp16 per step
    const int nl = tid & 127, kq8 = (tid >> 7) * 8;
    const int nn = n0 + nl;
    const int bidx = nn >> 12, sp = nn & 4095;
    const int y0 = sp >> 6, x0 = sp & 63;
    const __half* rb = reft + (size_t)bidx * HWSZ * CCH;

    float acc[4][4][4] = {};

    auto issue = [&](int s, int bf) {
        cp16(su32(Wsm + bf * CSTG + wm * 24 + wk8), wrow + s * 16);
        int tap = s >> 4;
        int ky = tap / 3, kx = tap - 3 * ky;
        int icq = (s & 15) * 16;
        int yv = y0 + ky - 1, xv = x0 + kx - 1;
        bool ok = ((unsigned)yv < 64u) && ((unsigned)xv < 64u);
        const __half* src = ok ? (rb + (size_t)((yv << 6) + xv) * CCH + icq + kq8)
                               : reft;
        cp16p(su32(Bsm + bf * CSTG + nl * 24 + kq8), src, ok ? 16 : 0);
    };

    const int l15 = lane & 15, lhi = (lane >> 4) * 8;
    const int mof = ((lane >> 4) & 1) * 8 + (lane & 7);
    const int kof = ((lane >> 3) & 1) * 8;
    const uint32_t aAddr = su32(Wsm + (warp_r * 64 + l15) * 24 + lhi);
    const uint32_t bAddr = su32(Bsm + (warp_c * 32 + mof) * 24 + kof);
    constexpr int STGB = CSTG * 2;  // stage stride in bytes

    constexpr int STEPS = KCONV / 16;   // 144
    #pragma unroll
    for (int i = 0; i < CPIPE - 1; ++i) { issue(i, i); cpcommit(); }

    for (int s = 0; s < STEPS; ++s) {
        cpwait<CPIPE - 2>();
        __syncthreads();
        const int bf = s & 3;
        uint32_t a[4][4], bq[2][4];
        #pragma unroll
        for (int rt = 0; rt < 4; ++rt)
            ldsm4(a[rt][0], a[rt][1], a[rt][2], a[rt][3],
                  aAddr + bf * STGB + rt * 16 * 48);
        #pragma unroll
        for (int cp = 0; cp < 2; ++cp)
            ldsm4(bq[cp][0], bq[cp][1], bq[cp][2], bq[cp][3],
                  bAddr + bf * STGB + cp * 16 * 48);
        #pragma unroll
        for (int rt = 0; rt < 4; ++rt)
            #pragma unroll
            for (int cp = 0; cp < 2; ++cp) {
                mma16(acc[rt][cp * 2],     a[rt], &bq[cp][0]);
                mma16(acc[rt][cp * 2 + 1], a[rt], &bq[cp][2]);
            }
        int nx = s + CPIPE - 1;
        if (nx < STEPS) issue(nx, nx & 3);
        cpcommit();
    }

    const int mrel0 = (m0 < 256) ? m0 : m0 - 256;
    if (m0 < 256) {
        // x1 -> transposed fp16 [B][HW][C]
        #pragma unroll
        for (int rt = 0; rt < 4; ++rt)
            #pragma unroll
            for (int ct = 0; ct < 4; ++ct) {
                int c = mrel0 + warp_r * 64 + rt * 16 + g;
                int n = n0 + warp_c * 32 + ct * 8 + 2 * t;
                int b2 = n >> 12, s2 = n & 4095;
                size_t base = ((size_t)b2 * HWSZ + s2) * CCH;
                x1t[base + c]           = __float2half(relu(acc[rt][ct][0]));
                x1t[base + CCH + c]     = __float2half(relu(acc[rt][ct][1]));
                x1t[base + c + 8]       = __float2half(relu(acc[rt][ct][2]));
                x1t[base + CCH + c + 8] = __float2half(relu(acc[rt][ct][3]));
            }
    } else {
        // v -> fp16 [B][C][HW]
        #pragma unroll
        for (int rt = 0; rt < 4; ++rt)
            #pragma unroll
            for (int ct = 0; ct < 4; ++ct) {
                int c = mrel0 + warp_r * 64 + rt * 16 + g;
                int n = n0 + warp_c * 32 + ct * 8 + 2 * t;
                int b2 = n >> 12, s2 = n & 4095;
                *(uint32_t*)&vout[((size_t)(b2 * CCH + c)) * HWSZ + s2] =
                    pack2(relu(acc[rt][ct][0]), relu(acc[rt][ct][1]));
                *(uint32_t*)&vout[((size_t)(b2 * CCH + c + 8)) * HWSZ + s2] =
                    pack2(relu(acc[rt][ct][2]), relu(acc[rt][ct][3]));
            }
    }
}

// ===========================================================================
// Kernel 2: Gram S = Xt Xt^T per batch (4096x4096, K=256), fp16 in, fp32 out.
// ===========================================================================
constexpr int GP = 3;
constexpr int G_TILE = 128 * 40;
constexpr int GRAM_SMEM = GP * 2 * G_TILE * 2;  // 61440 B

__global__ __launch_bounds__(256) void gram_mma(
    const __half* __restrict__ Xt, float* __restrict__ S)
{
    extern __shared__ __half sh[];
    __half* An = sh;
    __half* Bm = sh + GP * G_TILE;

    const int b = blockIdx.z;
    const __half* xb = Xt + (size_t)b * HWSZ * CCH;
    float* Sb = S + (size_t)b * HWSZ * HWSZ;

    const int tid = threadIdx.x, lane = tid & 31, wid = tid >> 5;
    const int warp_r = wid >> 2, warp_c = wid & 3;
    const int g = lane >> 2, t = lane & 3;
    const int m0 = blockIdx.x * 128, n0 = blockIdx.y * 128;

    float acc[4][4][4] = {};

    auto issue = [&](int ks, int bf) {
        #pragma unroll
        for (int j = 0; j < 2; ++j) {
            int e = tid + 256 * j;
            int row = e >> 2, kq = (e & 3) * 8;
            cp16(su32(An + bf * G_TILE + row * 40 + kq),
                 xb + (size_t)(n0 + row) * CCH + ks * 32 + kq);
            cp16(su32(Bm + bf * G_TILE + row * 40 + kq),
                 xb + (size_t)(m0 + row) * CCH + ks * 32 + kq);
        }
    };

    const int l15 = lane & 15, lhi = (lane >> 4) * 8;
    const int mof = ((lane >> 4) & 1) * 8 + (lane & 7);
    const int kof = ((lane >> 3) & 1) * 8;
    const uint32_t aBase = su32(An + (warp_r * 64 + l15) * 40 + lhi);
    const uint32_t bBase = su32(Bm + (warp_c * 32 + mof) * 40 + kof);
    constexpr int BUFB = G_TILE * 2;

    constexpr int STEPS = CCH / 32;  // 8
    #pragma unroll
    for (int i = 0; i < GP - 1; ++i) { issue(i, i); cpcommit(); }

    for (int s = 0; s < STEPS; ++s) {
        cpwait<GP - 2>();
        __syncthreads();
        const int bf = s % GP;
        #pragma unroll
        for (int kk = 0; kk < 2; ++kk) {
            uint32_t a[4][4], bq[2][4];
            #pragma unroll
            for (int rt = 0; rt < 4; ++rt)
                ldsm4(a[rt][0], a[rt][1], a[rt][2], a[rt][3],
                      aBase + bf * BUFB + rt * 16 * 80 + kk * 32);
            #pragma unroll
            for (int cp = 0; cp < 2; ++cp)
                ldsm4(bq[cp][0], bq[cp][1], bq[cp][2], bq[cp][3],
                      bBase + bf * BUFB + cp * 16 * 80 + kk * 32);
            #pragma unroll
            for (int rt = 0; rt < 4; ++rt)
                #pragma unroll
                for (int cp = 0; cp < 2; ++cp) {
                    mma16(acc[rt][cp * 2],     a[rt], &bq[cp][0]);
                    mma16(acc[rt][cp * 2 + 1], a[rt], &bq[cp][2]);
                }
        }
        int nx = s + GP - 1;
        if (nx < STEPS) issue(nx, nx % GP);
        cpcommit();
    }

    #pragma unroll
    for (int rt = 0; rt < 4; ++rt)
        #pragma unroll
        for (int ct = 0; ct < 4; ++ct) {
            int n = n0 + warp_r * 64 + rt * 16 + g;
            int m = m0 + warp_c * 32 + ct * 8 + 2 * t;
            *(float2*)(Sb + (size_t)n * HWSZ + m) =
                make_float2(acc[rt][ct][0], acc[rt][ct][1]);
            *(float2*)(Sb + (size_t)(n + 8) * HWSZ + m) =
                make_float2(acc[rt][ct][2], acc[rt][ct][3]);
        }
}

// ===========================================================================
// Kernel 3: row softmax of S (fp32 in), fp16 P out.
// ===========================================================================
__device__ __forceinline__ float warpMax(float v) {
    #pragma unroll
    for (int o = 16; o; o >>= 1) v = fmaxf(v, __shfl_xor_sync(0xffffffffu, v, o));
    return v;
}
__device__ __forceinline__ float warpSum(float v) {
    #pragma unroll
    for (int o = 16; o; o >>= 1) v += __shfl_xor_sync(0xffffffffu, v, o);
    return v;
}

__global__ __launch_bounds__(256) void softmax_kernel(
    const float* __restrict__ S, __half* __restrict__ P)
{
    const size_t roff = (size_t)blockIdx.y * HWSZ * HWSZ + (size_t)blockIdx.x * HWSZ;
    const float* p = S + roff;
    __half* q = P + roff;
    const int tid = threadIdx.x;
    __shared__ float red[8];

    float vals[16];
    float mx = -CUDART_INF_F;
    #pragma unroll
    for (int i = 0; i < 16; ++i) {
        vals[i] = p[tid + i * 256];
        mx = fmaxf(mx, vals[i]);
    }
    mx = warpMax(mx);
    if ((tid & 31) == 0) red[tid >> 5] = mx;
    __syncthreads();
    {
        float m = red[tid & 7];
        #pragma unroll
        for (int o = 4; o; o >>= 1) m = fmaxf(m, __shfl_xor_sync(0xffffffffu, m, o));
        mx = m;
    }
    float sum = 0.f;
    #pragma unroll
    for (int i = 0; i < 16; ++i) {
        vals[i] = __expf(vals[i] - mx);
        sum += vals[i];
    }
    sum = warpSum(sum);
    __syncthreads();
    if ((tid & 31) == 0) red[tid >> 5] = sum;
    __syncthreads();
    {
        float s = red[tid & 7];
        #pragma unroll
        for (int o = 4; o; o >>= 1) s += __shfl_xor_sync(0xffffffffu, s, o);
        sum = s;
    }
    float inv = 1.f / sum;
    #pragma unroll
    for (int i = 0; i < 16; ++i)
        q[tid + i * 256] = __float2half(vals[i] * inv);
}

// ===========================================================================
// Kernel 4: A = V P^T (256 x 4096, K=4096) fp16, epilogue out = gamma*A + ref.
// ===========================================================================
constexpr int AV_SMEM = GRAM_SMEM;

__global__ __launch_bounds__(256) void av_mma(
    const __half* __restrict__ V, const __half* __restrict__ P,
    const float* __restrict__ ref, const float* __restrict__ gammap,
    float* __restrict__ out)
{
    extern __shared__ __half sh[];
    __half* Vs = sh;
    __half* Ps = sh + GP * G_TILE;

    const int b = blockIdx.z;
    const __half* vb = V + (size_t)b * CCH * HWSZ;
    const __half* pb = P + (size_t)b * HWSZ * HWSZ;

    const int tid = threadIdx.x, lane = tid & 31, wid = tid >> 5;
    const int warp_r = wid >> 2, warp_c = wid & 3;
    const int g = lane >> 2, t = lane & 3;
    const int m0 = blockIdx.x * 128, c0 = blockIdx.y * 128;

    float acc[4][4][4] = {};

    auto issue = [&](int ks, int bf) {
        #pragma unroll
        for (int j = 0; j < 2; ++j) {
            int e = tid + 256 * j;
            int row = e >> 2, kq = (e & 3) * 8;
            cp16(su32(Vs + bf * G_TILE + row * 40 + kq),
                 vb + (size_t)(c0 + row) * HWSZ + ks * 32 + kq);
            cp16(su32(Ps + bf * G_TILE + row * 40 + kq),
                 pb + (size_t)(m0 + row) * HWSZ + ks * 32 + kq);
        }
    };

    const int l15 = lane & 15, lhi = (lane >> 4) * 8;
    const int mof = ((lane >> 4) & 1) * 8 + (lane & 7);
    const int kof = ((lane >> 3) & 1) * 8;
    const uint32_t aBase = su32(Vs + (warp_r * 64 + l15) * 40 + lhi);
    const uint32_t bBase = su32(Ps + (warp_c * 32 + mof) * 40 + kof);
    constexpr int BUFB = G_TILE * 2;

    constexpr int STEPS = HWSZ / 32;  // 128
    #pragma unroll
    for (int i = 0; i < GP - 1; ++i) { issue(i, i); cpcommit(); }

    for (int s = 0; s < STEPS; ++s) {
        cpwait<GP - 2>();
        __syncthreads();
        const int bf = s % GP;
        #pragma unroll
        for (int kk = 0; kk < 2; ++kk) {
            uint32_t a[4][4], bq[2][4];
            #pragma unroll
            for (int rt = 0; rt < 4; ++rt)
                ldsm4(a[rt][0], a[rt][1], a[rt][2], a[rt][3],
                      aBase + bf * BUFB + rt * 16 * 80 + kk * 32);
            #pragma unroll
            for (int cp = 0; cp < 2; ++cp)
                ldsm4(bq[cp][0], bq[cp][1], bq[cp][2], bq[cp][3],
                      bBase + bf * BUFB + cp * 16 * 80 + kk * 32);
            #pragma unroll
            for (int rt = 0; rt < 4; ++rt)
                #pragma unroll
                for (int cp = 0; cp < 2; ++cp) {
                    mma16(acc[rt][cp * 2],     a[rt], &bq[cp][0]);
                    mma16(acc[rt][cp * 2 + 1], a[rt], &bq[cp][2]);
                }
        }
        int nx = s + GP - 1;
        if (nx < STEPS) issue(nx, nx % GP);
        cpcommit();
    }

    const float gm = *gammap;
    #pragma unroll
    for (int rt = 0; rt < 4; ++rt)
        #pragma unroll
        for (int ct = 0; ct < 4; ++ct) {
            int c = c0 + warp_r * 64 + rt * 16 + g;
            int m = m0 + warp_c * 32 + ct * 8 + 2 * t;
            size_t a0 = ((size_t)(b * CCH + c)) * HWSZ + m;
            size_t a1 = ((size_t)(b * CCH + c + 8)) * HWSZ + m;
            float2 r0 = *(const float2*)(ref + a0);
            float2 r1 = *(const float2*)(ref + a1);
            *(float2*)(out + a0) = make_float2(acc[rt][ct][0] * gm + r0.x,
                                               acc[rt][ct][1] * gm + r0.y);
            *(float2*)(out + a1) = make_float2(acc[rt][ct][2] * gm + r1.x,
                                               acc[rt][ct][3] * gm + r1.y);
        }
}

// ---------------------------------------------------------------------------
// Launch. Inputs: inputs, ref, w1, w2, gamma. (conv on `inputs` is dead code.)
// ---------------------------------------------------------------------------
extern "C" void kernel_launch(void* const* d_in, const int* in_sizes, int n_in,
                              void* d_out, int out_size)
{
    const float* ref   = (const float*)d_in[1];
    const float* w1    = (const float*)d_in[2];
    const float* w2    = (const float*)d_in[3];
    const float* gamma = (const float*)d_in[4];
    float* out = (float*)d_out;

    __half* reft = nullptr; cudaGetSymbolAddress((void**)&reft, g_reft);
    __half* wr   = nullptr; cudaGetSymbolAddress((void**)&wr,   g_wr);
    __half* x1t  = nullptr; cudaGetSymbolAddress((void**)&x1t,  g_x1t);
    __half* vh   = nullptr; cudaGetSymbolAddress((void**)&vh,   g_vh);
    float*  S    = nullptr; cudaGetSymbolAddress((void**)&S,    g_S);
    __half* P    = nullptr; cudaGetSymbolAddress((void**)&P,    g_P);

    cudaFuncSetAttribute(conv_mma, cudaFuncAttributeMaxDynamicSharedMemorySize, CONV_SMEM);
    cudaFuncSetAttribute(gram_mma, cudaFuncAttributeMaxDynamicSharedMemorySize, GRAM_SMEM);
    cudaFuncSetAttribute(av_mma,   cudaFuncAttributeMaxDynamicSharedMemorySize, AV_SMEM);

    transpose_ref<<<dim3(128, 8, BATCH), 256>>>(ref, reft);
    reorder_w<<<512, 256>>>(w1, w2, wr);
    conv_mma<<<dim3(128, 4), 256, CONV_SMEM>>>(reft, wr, x1t, vh);
    gram_mma<<<dim3(32, 32, BATCH), 256, GRAM_SMEM>>>(x1t, S);
    softmax_kernel<<<dim3(HWSZ, BATCH), 256>>>(S, P);
    av_mma<<<dim3(32, 2, BATCH), 256, AV_SMEM>>>(vh, P, ref, gamma, out);
}